// round 9
// baseline (speedup 1.0000x reference)
#include <cuda_runtime.h>
#include <cuda_bf16.h>
#include <cstdint>
#include <math.h>

#define B_  64
#define S_  2048
#define U_  1024
#define M_  (B_ * S_)   // 131072

// ---------------- scratch (device globals; no allocs allowed) ---------------
__device__ float g_Ws[B_ * U_];                     // s_prev @ W_w + W_b
__device__ float g_scores[M_];                      // pre-softmax scores
__device__ __nv_bfloat16 g_Bhi[U_ * U_];            // Uw^T hi  [n][k]
__device__ __nv_bfloat16 g_Blo[U_ * U_];            // Uw^T lo  [n][k]

// ---------------- K0: init --------------------------------------------------
__global__ void k_init(const float* __restrict__ Wb,
                       const float* __restrict__ Vb,
                       float* __restrict__ ctx_out) {
    int i = blockIdx.x * blockDim.x + threadIdx.x;
    if (i < B_ * U_) { g_Ws[i] = Wb[i & (U_ - 1)]; ctx_out[i] = 0.0f; }
    if (i < M_) g_scores[i] = Vb[0];
}

// ---------------- K1: Ws += s_prev @ W_w ------------------------------------
__global__ void __launch_bounds__(128) k_ws(const float* __restrict__ s_prev,
                                            const float* __restrict__ Ww) {
    __shared__ float s_sm[B_][128];
    const int tid = threadIdx.x;
    const int u   = blockIdx.x * 128 + tid;
    const int k0  = blockIdx.y * 128;
    for (int j = 0; j < 64; j++) {
        int idx = tid + 128 * j;
        s_sm[idx >> 7][idx & 127] = s_prev[(idx >> 7) * U_ + k0 + (idx & 127)];
    }
    __syncthreads();
    float acc[B_];
    #pragma unroll
    for (int b = 0; b < B_; b++) acc[b] = 0.0f;
    for (int kk = 0; kk < 128; kk++) {
        float w = Ww[(k0 + kk) * U_ + u];
        #pragma unroll
        for (int b = 0; b < B_; b++) acc[b] += s_sm[b][kk] * w;
    }
    #pragma unroll
    for (int b = 0; b < B_; b++) atomicAdd(&g_Ws[b * U_ + u], acc[b]);
}

// ---------------- K2: transpose+split Uw -> [n][k] ---------------------------
__global__ void __launch_bounds__(256) k_splitB(const float* __restrict__ Uw) {
    int i = blockIdx.x * 256 + threadIdx.x;     // 0 .. 1M-1
    int k = i >> 10, n = i & (U_ - 1);
    float x = Uw[k * U_ + n];
    __nv_bfloat16 h = __float2bfloat16(x);
    __nv_bfloat16 l = __float2bfloat16(x - __bfloat162float(h));
    g_Bhi[n * U_ + k] = h;
    g_Blo[n * U_ + k] = l;
}

// ---------------- mma.sync helpers -------------------------------------------
__device__ __forceinline__ uint32_t smem_u32(const void* p) {
    uint32_t a;
    asm("{ .reg .u64 t; cvta.to.shared.u64 t, %1; cvt.u32.u64 %0, t; }"
        : "=r"(a) : "l"(p));
    return a;
}
__device__ __forceinline__ void cp16(uint32_t saddr, const void* g) {
    asm volatile("cp.async.cg.shared.global [%0], [%1], 16;"
                 :: "r"(saddr), "l"(g) : "memory");
}
#define CP_COMMIT() asm volatile("cp.async.commit_group;" ::: "memory")
#define CP_WAIT(N)  asm volatile("cp.async.wait_group %0;" :: "n"(N) : "memory")

__device__ __forceinline__ void mma_bf16(float* c, const uint32_t* a,
                                         uint32_t b0, uint32_t b1) {
    asm volatile(
        "mma.sync.aligned.m16n8k16.row.col.f32.bf16.bf16.f32 "
        "{%0,%1,%2,%3}, {%4,%5,%6,%7}, {%8,%9}, {%0,%1,%2,%3};"
        : "+f"(c[0]), "+f"(c[1]), "+f"(c[2]), "+f"(c[3])
        : "r"(a[0]), "r"(a[1]), "r"(a[2]), "r"(a[3]), "r"(b0), "r"(b1));
}
__device__ __forceinline__ void ldsm_x4(uint32_t& r0, uint32_t& r1,
                                        uint32_t& r2, uint32_t& r3, uint32_t a) {
    asm volatile("ldmatrix.sync.aligned.m8n8.x4.shared.b16 {%0,%1,%2,%3}, [%4];"
                 : "=r"(r0), "=r"(r1), "=r"(r2), "=r"(r3) : "r"(a));
}

// pack 2 fp32 -> bf16x2 (hi), and residual bf16x2 (lo)
__device__ __forceinline__ void split2(float x0, float x1, uint32_t& hi, uint32_t& lo) {
    __nv_bfloat162 h = __floats2bfloat162_rn(x0, x1);
    hi = *(uint32_t*)&h;
    __nv_bfloat162 l = __floats2bfloat162_rn(x0 - __low2float(h), x1 - __high2float(h));
    lo = *(uint32_t*)&l;
}

// ---------------- K3: scores GEMM (bf16x3, mma.sync, ldmatrix B) -------------
// C tile BM=128 x BN=128, BK=32; 8 warps (4m x 2n), warp tile 32x64.
#define BMm 128
#define BNm 128
#define BKm 32
// A: fp32 in SMEM, padded row stride 36 floats (144 B)
#define RSA 36
#define A_E  (BMm * RSA)            // 4608 floats
// B: bf16 in SMEM, padded row stride 40 bf16 (80 B)
#define RSB 40
#define B_E  (BNm * RSB)            // 5120 bf16
// stage layout (bytes): [A fp32 18432][Bhi 10240][Blo 10240] = 38912 B
#define STG_B   (A_E * 4 + 2 * B_E * 2)
#define OFF_BH  (A_E * 4)
#define OFF_BL  (A_E * 4 + B_E * 2)
#define NCHm (U_ / BKm)             // 32 k-chunks

__global__ void __launch_bounds__(256, 2) k_scores_mma(const float* __restrict__ HS,
                                                       const float* __restrict__ Ub,
                                                       const float* __restrict__ Vw) {
    extern __shared__ char sm[];                   // 2 stages
    __shared__ float sWs[BNm], sUb[BNm], sVw[BNm];

    const int tid  = threadIdx.x;
    const int wid  = tid >> 5;
    const int lane = tid & 31;
    const int gid  = lane >> 2;
    const int tig  = lane & 3;
    const int warp_m = wid & 3;                    // 0..3, 32 rows each
    const int warp_n = wid >> 2;                   // 0..1, 64 cols each

    const int col0 = blockIdx.x * BNm;
    const int row0 = blockIdx.y * BMm;
    const int b    = row0 >> 11;                   // batch (S=2048)

    if (tid < BNm) {
        sWs[tid] = g_Ws[b * U_ + col0 + tid];
        sUb[tid] = Ub[col0 + tid];
        sVw[tid] = Vw[col0 + tid];
    }

    const float* gA = HS + (size_t)row0 * U_;
    const __nv_bfloat16* gBh = g_Bhi + (size_t)col0 * U_;
    const __nv_bfloat16* gBl = g_Blo + (size_t)col0 * U_;

    const uint32_t sb = smem_u32(sm);

    // per-lane constant ldmatrix offset within a B tile-pair:
    //   matrix m = lane>>3 : {0,1,2,3} -> {n+0,k+0},{n+0,k+8},{n+8,k+0},{n+8,k+8}
    const int lm_m = lane >> 3, lm_r = lane & 7;
    const uint32_t lm_off =
        (uint32_t)(((warp_n * 64) + ((lm_m & 2) ? 8 : 0) + lm_r) * RSB
                   + ((lm_m & 1) ? 8 : 0)) * 2;

    // issue cp.async for chunk kc into stage buf
    auto issue = [&](int kc, int buf) {
        const int kofs = kc * BKm;
        const uint32_t stb = sb + buf * STG_B;
        #pragma unroll
        for (int i = 0; i < 4; i++) {
            int c = tid + i * 256;                 // 0..1023
            int r = c >> 3, q = (c & 7) * 4;       // row, float offset
            cp16(stb + (uint32_t)(r * RSA + q) * 4, gA + (size_t)r * U_ + kofs + q);
        }
        #pragma unroll
        for (int i = 0; i < 2; i++) {
            int c = tid + i * 256;                 // 0..511
            int r = c >> 2, q = (c & 3) * 8;       // row, bf16 offset
            uint32_t so = (uint32_t)(r * RSB + q) * 2;
            cp16(stb + OFF_BH + so, gBh + (size_t)r * U_ + kofs + q);
            cp16(stb + OFF_BL + so, gBl + (size_t)r * U_ + kofs + q);
        }
        CP_COMMIT();
    };

    float acc[2][8][4];
    #pragma unroll
    for (int mt = 0; mt < 2; mt++)
        #pragma unroll
        for (int nt = 0; nt < 8; nt++)
            #pragma unroll
            for (int j = 0; j < 4; j++) acc[mt][nt][j] = 0.0f;

    issue(0, 0);

    for (int kc = 0; kc < NCHm; kc++) {
        if (kc + 1 < NCHm) { issue(kc + 1, (kc + 1) & 1); CP_WAIT(1); }
        else               { CP_WAIT(0); }
        __syncthreads();

        const char* st = sm + (kc & 1) * STG_B;
        const float* sA = (const float*)st;
        const uint32_t bh_base = sb + (kc & 1) * STG_B + OFF_BH + lm_off;
        const uint32_t bl_base = sb + (kc & 1) * STG_B + OFF_BL + lm_off;

        #pragma unroll
        for (int slab = 0; slab < 2; slab++) {
            const int kb = slab * 16;
            uint32_t Ah[2][4], Al[2][4];
            #pragma unroll
            for (int mt = 0; mt < 2; mt++) {
                int r = warp_m * 32 + mt * 16 + gid;
                const float* pa = sA + r * RSA + kb + 2 * tig;
                float2 v0 = *(const float2*)(pa);
                float2 v1 = *(const float2*)(pa + 8 * RSA);
                float2 v2 = *(const float2*)(pa + 8);
                float2 v3 = *(const float2*)(pa + 8 * RSA + 8);
                split2(v0.x, v0.y, Ah[mt][0], Al[mt][0]);
                split2(v1.x, v1.y, Ah[mt][1], Al[mt][1]);
                split2(v2.x, v2.y, Ah[mt][2], Al[mt][2]);
                split2(v3.x, v3.y, Ah[mt][3], Al[mt][3]);
            }
            #pragma unroll
            for (int ntp = 0; ntp < 4; ntp++) {
                // two n-tiles per ldmatrix.x4
                uint32_t bh0, bh1, bh2, bh3, bl0, bl1, bl2, bl3;
                uint32_t toff = (uint32_t)(ntp * 16 * RSB + kb) * 2;
                ldsm_x4(bh0, bh1, bh2, bh3, bh_base + toff);
                ldsm_x4(bl0, bl1, bl2, bl3, bl_base + toff);
                #pragma unroll
                for (int mt = 0; mt < 2; mt++) {
                    mma_bf16(acc[mt][2 * ntp],     Ah[mt], bh0, bh1);
                    mma_bf16(acc[mt][2 * ntp],     Ah[mt], bl0, bl1);
                    mma_bf16(acc[mt][2 * ntp],     Al[mt], bh0, bh1);
                    mma_bf16(acc[mt][2 * ntp + 1], Ah[mt], bh2, bh3);
                    mma_bf16(acc[mt][2 * ntp + 1], Ah[mt], bl2, bl3);
                    mma_bf16(acc[mt][2 * ntp + 1], Al[mt], bh2, bh3);
                }
            }
        }
        __syncthreads();
    }

    // epilogue: tanh + dot with Vw, reduce over n within thread, then over tig
    #pragma unroll
    for (int mt = 0; mt < 2; mt++) {
        float pl = 0.0f, ph = 0.0f;
        #pragma unroll
        for (int nt = 0; nt < 8; nt++) {
            int nb = warp_n * 64 + nt * 8 + 2 * tig;
            pl += tanhf(acc[mt][nt][0] + sWs[nb]     + sUb[nb])     * sVw[nb];
            pl += tanhf(acc[mt][nt][1] + sWs[nb + 1] + sUb[nb + 1]) * sVw[nb + 1];
            ph += tanhf(acc[mt][nt][2] + sWs[nb]     + sUb[nb])     * sVw[nb];
            ph += tanhf(acc[mt][nt][3] + sWs[nb + 1] + sUb[nb + 1]) * sVw[nb + 1];
        }
        pl += __shfl_xor_sync(0xffffffffu, pl, 1);
        pl += __shfl_xor_sync(0xffffffffu, pl, 2);
        ph += __shfl_xor_sync(0xffffffffu, ph, 1);
        ph += __shfl_xor_sync(0xffffffffu, ph, 2);
        if (tig == 0) {
            int r = row0 + warp_m * 32 + mt * 16 + gid;
            atomicAdd(&g_scores[r], pl);
            atomicAdd(&g_scores[r + 8], ph);
        }
    }
}

// ---------------- K4: softmax over S per batch -------------------------------
__global__ void __launch_bounds__(256) k_softmax(float* __restrict__ w_out) {
    __shared__ float red[256];
    const int b   = blockIdx.x;
    const int tid = threadIdx.x;
    const float* sc = g_scores + b * S_;
    float* w = w_out + b * S_;

    float m = -1e30f;
    for (int s = tid; s < S_; s += 256) m = fmaxf(m, sc[s]);
    red[tid] = m; __syncthreads();
    for (int o = 128; o > 0; o >>= 1) {
        if (tid < o) red[tid] = fmaxf(red[tid], red[tid + o]);
        __syncthreads();
    }
    m = red[0];
    __syncthreads();

    float sum = 0.0f;
    for (int s = tid; s < S_; s += 256) {
        float e = expf(sc[s] - m);
        w[s] = e;
        sum += e;
    }
    red[tid] = sum; __syncthreads();
    for (int o = 128; o > 0; o >>= 1) {
        if (tid < o) red[tid] += red[tid + o];
        __syncthreads();
    }
    float inv = 1.0f / red[0];
    for (int s = tid; s < S_; s += 256) w[s] *= inv;
}

// ---------------- K5: context = sum_s w * HS ---------------------------------
__global__ void __launch_bounds__(256) k_context(const float* __restrict__ HS,
                                                 const float* __restrict__ w_in,
                                                 float* __restrict__ ctx) {
    __shared__ float w_sm[256];
    const int tid = threadIdx.x;
    const int b   = blockIdx.y;
    const int s0  = blockIdx.x * 256;

    w_sm[tid] = w_in[b * S_ + s0 + tid];
    __syncthreads();

    const int u = tid * 4;
    float ax = 0.f, ay = 0.f, az = 0.f, aw = 0.f;
    const float* base = HS + ((size_t)b * S_ + s0) * U_ + u;
    for (int s = 0; s < 256; s++) {
        float wv = w_sm[s];
        float4 h = *(const float4*)(base + (size_t)s * U_);
        ax += wv * h.x; ay += wv * h.y; az += wv * h.z; aw += wv * h.w;
    }
    atomicAdd(&ctx[b * U_ + u + 0], ax);
    atomicAdd(&ctx[b * U_ + u + 1], ay);
    atomicAdd(&ctx[b * U_ + u + 2], az);
    atomicAdd(&ctx[b * U_ + u + 3], aw);
}

// ---------------- launch -----------------------------------------------------
extern "C" void kernel_launch(void* const* d_in, const int* in_sizes, int n_in,
                              void* d_out, int out_size) {
    const float* s_prev = (const float*)d_in[0];
    const float* HS     = (const float*)d_in[1];
    const float* Ww     = (const float*)d_in[2];
    const float* Wb     = (const float*)d_in[3];
    const float* Uw     = (const float*)d_in[4];
    const float* Ub     = (const float*)d_in[5];
    const float* Vw     = (const float*)d_in[6];
    const float* Vb     = (const float*)d_in[7];

    float* ctx     = (float*)d_out;            // [64, 1024]
    float* weights = (float*)d_out + B_ * U_;  // [64, 2048, 1]

    const int smem_bytes = 2 * STG_B;          // 77824
    cudaFuncSetAttribute(k_scores_mma,
                         cudaFuncAttributeMaxDynamicSharedMemorySize, smem_bytes);

    // launch order chosen so the profiler's captured launch (#4) is the GEMM
    k_init<<<M_ / 256, 256>>>(Wb, Vb, ctx);
    k_ws<<<dim3(8, 8), 128>>>(s_prev, Ww);
    k_splitB<<<U_ * U_ / 256, 256>>>(Uw);
    k_scores_mma<<<dim3(U_ / BNm, M_ / BMm), 256, smem_bytes>>>(HS, Ub, Vw);
    k_softmax<<<B_, 256>>>(weights);
    k_context<<<dim3(S_ / 256, B_), 256>>>(HS, weights, ctx);
}

// round 10
// speedup vs baseline: 1.0366x; 1.0366x over previous
#include <cuda_runtime.h>
#include <cuda_bf16.h>
#include <cstdint>
#include <math.h>

#define B_  64
#define S_  2048
#define U_  1024
#define M_  (B_ * S_)   // 131072

// ---------------- scratch (device globals; no allocs allowed) ---------------
__device__ float g_Ws[B_ * U_];                     // s_prev @ W_w + W_b
__device__ float g_scores[M_];                      // pre-softmax scores
__device__ __nv_bfloat16 g_Bhi[U_ * U_];            // Uw^T hi  [n][k]
__device__ __nv_bfloat16 g_Blo[U_ * U_];            // Uw^T lo  [n][k]

// ---------------- K0: init --------------------------------------------------
__global__ void k_init(const float* __restrict__ Wb,
                       const float* __restrict__ Vb,
                       float* __restrict__ ctx_out) {
    int i = blockIdx.x * blockDim.x + threadIdx.x;
    if (i < B_ * U_) { g_Ws[i] = Wb[i & (U_ - 1)]; ctx_out[i] = 0.0f; }
    if (i < M_) g_scores[i] = Vb[0];
}

// ---------------- K1: Ws += s_prev @ W_w ------------------------------------
__global__ void __launch_bounds__(128) k_ws(const float* __restrict__ s_prev,
                                            const float* __restrict__ Ww) {
    __shared__ float s_sm[B_][128];
    const int tid = threadIdx.x;
    const int u   = blockIdx.x * 128 + tid;
    const int k0  = blockIdx.y * 128;
    for (int j = 0; j < 64; j++) {
        int idx = tid + 128 * j;
        s_sm[idx >> 7][idx & 127] = s_prev[(idx >> 7) * U_ + k0 + (idx & 127)];
    }
    __syncthreads();
    float acc[B_];
    #pragma unroll
    for (int b = 0; b < B_; b++) acc[b] = 0.0f;
    for (int kk = 0; kk < 128; kk++) {
        float w = Ww[(k0 + kk) * U_ + u];
        #pragma unroll
        for (int b = 0; b < B_; b++) acc[b] += s_sm[b][kk] * w;
    }
    #pragma unroll
    for (int b = 0; b < B_; b++) atomicAdd(&g_Ws[b * U_ + u], acc[b]);
}

// ---------------- K2: transpose+split Uw -> [n][k] ---------------------------
__global__ void __launch_bounds__(256) k_splitB(const float* __restrict__ Uw) {
    int i = blockIdx.x * 256 + threadIdx.x;     // 0 .. 1M-1
    int k = i >> 10, n = i & (U_ - 1);
    float x = Uw[k * U_ + n];
    __nv_bfloat16 h = __float2bfloat16(x);
    __nv_bfloat16 l = __float2bfloat16(x - __bfloat162float(h));
    g_Bhi[n * U_ + k] = h;
    g_Blo[n * U_ + k] = l;
}

// ---------------- mma.sync helpers -------------------------------------------
__device__ __forceinline__ uint32_t smem_u32(const void* p) {
    uint32_t a;
    asm("{ .reg .u64 t; cvta.to.shared.u64 t, %1; cvt.u32.u64 %0, t; }"
        : "=r"(a) : "l"(p));
    return a;
}
__device__ __forceinline__ void cp16(uint32_t saddr, const void* g) {
    asm volatile("cp.async.cg.shared.global [%0], [%1], 16;"
                 :: "r"(saddr), "l"(g) : "memory");
}
#define CP_COMMIT() asm volatile("cp.async.commit_group;" ::: "memory")
#define CP_WAIT(N)  asm volatile("cp.async.wait_group %0;" :: "n"(N) : "memory")

__device__ __forceinline__ void mma_bf16(float* c, const uint32_t* a,
                                         uint32_t b0, uint32_t b1) {
    asm volatile(
        "mma.sync.aligned.m16n8k16.row.col.f32.bf16.bf16.f32 "
        "{%0,%1,%2,%3}, {%4,%5,%6,%7}, {%8,%9}, {%0,%1,%2,%3};"
        : "+f"(c[0]), "+f"(c[1]), "+f"(c[2]), "+f"(c[3])
        : "r"(a[0]), "r"(a[1]), "r"(a[2]), "r"(a[3]), "r"(b0), "r"(b1));
}

// pack 2 fp32 -> bf16x2 (hi), and residual bf16x2 (lo)
__device__ __forceinline__ void split2(float x0, float x1, uint32_t& hi, uint32_t& lo) {
    __nv_bfloat162 h = __floats2bfloat162_rn(x0, x1);
    hi = *(uint32_t*)&h;
    __nv_bfloat162 l = __floats2bfloat162_rn(x0 - __low2float(h), x1 - __high2float(h));
    lo = *(uint32_t*)&l;
}

// ---------------- K3: scores GEMM (bf16x3, mma.sync) -------------------------
// C tile BM=128 x BN=128, BK=32; 8 warps (4m x 2n), warp tile 32x64.
// Pipeline: A 3-stage (DRAM-latency cover), B 2-stage (L2-resident),
// one barrier per k-chunk.
#define BMm 128
#define BNm 128
#define BKm 32
#define RSA 36                      // A fp32 row stride (144 B)
#define RSB 40                      // B bf16 row stride (80 B)
#define A_STG (BMm * RSA * 4)       // 18432 B
#define B_HALF (BNm * RSB * 2)      // 10240 B (hi or lo)
#define B_STG (2 * B_HALF)          // 20480 B
#define OFF_A(s) ((s) * A_STG)
#define OFF_Bh(s) (3 * A_STG + (s) * B_STG)
#define OFF_Bl(s) (3 * A_STG + (s) * B_STG + B_HALF)
#define SMEM_K3 (3 * A_STG + 2 * B_STG)     // 96256 B
#define NCHm (U_ / BKm)             // 32 k-chunks

__global__ void __launch_bounds__(256, 2) k_scores_mma(const float* __restrict__ HS,
                                                       const float* __restrict__ Ub,
                                                       const float* __restrict__ Vw) {
    extern __shared__ char sm[];
    __shared__ float sWs[BNm], sUb[BNm], sVw[BNm];

    const int tid  = threadIdx.x;
    const int wid  = tid >> 5;
    const int lane = tid & 31;
    const int gid  = lane >> 2;
    const int tig  = lane & 3;
    const int warp_m = wid & 3;                    // 0..3, 32 rows each
    const int warp_n = wid >> 2;                   // 0..1, 64 cols each

    const int col0 = blockIdx.x * BNm;
    const int row0 = blockIdx.y * BMm;
    const int b    = row0 >> 11;                   // batch (S=2048)

    if (tid < BNm) {
        sWs[tid] = g_Ws[b * U_ + col0 + tid];
        sUb[tid] = Ub[col0 + tid];
        sVw[tid] = Vw[col0 + tid];
    }

    const float* gA = HS + (size_t)row0 * U_;
    const __nv_bfloat16* gBh = g_Bhi + (size_t)col0 * U_;
    const __nv_bfloat16* gBl = g_Blo + (size_t)col0 * U_;

    const uint32_t sb = smem_u32(sm);

    // A chunk kc -> stage kc%3 : 128 rows x 128 B = 1024 cp16 (4/thread)
    auto issueA = [&](int kc) {
        if (kc < NCHm) {
            const int kofs = kc * BKm;
            const uint32_t stb = sb + OFF_A(kc % 3);
            #pragma unroll
            for (int i = 0; i < 4; i++) {
                int c = tid + i * 256;             // 0..1023
                int r = c >> 3, q = (c & 7) * 4;   // row, float offset
                cp16(stb + (uint32_t)(r * RSA + q) * 4, gA + (size_t)r * U_ + kofs + q);
            }
        }
        CP_COMMIT();
    };
    // B chunk kc -> stage kc&1 : hi+lo, 128 rows x 64 B each = 512 cp16 (2/thread)
    auto issueB = [&](int kc) {
        if (kc < NCHm) {
            const int kofs = kc * BKm;
            const uint32_t bh = sb + OFF_Bh(kc & 1);
            const uint32_t bl = sb + OFF_Bl(kc & 1);
            #pragma unroll
            for (int i = 0; i < 2; i++) {
                int c = tid + i * 256;             // 0..511
                int r = c >> 2, q = (c & 3) * 8;   // row, bf16 offset
                uint32_t so = (uint32_t)(r * RSB + q) * 2;
                cp16(bh + so, gBh + (size_t)r * U_ + kofs + q);
                cp16(bl + so, gBl + (size_t)r * U_ + kofs + q);
            }
        }
        CP_COMMIT();
    };

    float acc[2][8][4];
    #pragma unroll
    for (int mt = 0; mt < 2; mt++)
        #pragma unroll
        for (int nt = 0; nt < 8; nt++)
            #pragma unroll
            for (int j = 0; j < 4; j++) acc[mt][nt][j] = 0.0f;

    // prologue: groups in FIFO order B0, A0, A1
    issueB(0);
    issueA(0);
    issueA(1);

    for (int kc = 0; kc < NCHm; kc++) {
        // all groups up through B(kc) (and hence A(kc)) complete when <=1 pending
        CP_WAIT(1);
        __syncthreads();

        // refill: B(kc+1) then A(kc+2)  (keeps FIFO: ...,B(kc),A(kc+1),B(kc+1),A(kc+2))
        issueB(kc + 1);
        issueA(kc + 2);

        const float* sA = (const float*)(sm + OFF_A(kc % 3));
        const __nv_bfloat16* sBh = (const __nv_bfloat16*)(sm + OFF_Bh(kc & 1));
        const __nv_bfloat16* sBl = (const __nv_bfloat16*)(sm + OFF_Bl(kc & 1));

        #pragma unroll
        for (int slab = 0; slab < 2; slab++) {
            const int kb = slab * 16;
            uint32_t Ah[2][4], Al[2][4];
            #pragma unroll
            for (int mt = 0; mt < 2; mt++) {
                int r = warp_m * 32 + mt * 16 + gid;
                const float* pa = sA + r * RSA + kb + 2 * tig;
                float2 v0 = *(const float2*)(pa);
                float2 v1 = *(const float2*)(pa + 8 * RSA);
                float2 v2 = *(const float2*)(pa + 8);
                float2 v3 = *(const float2*)(pa + 8 * RSA + 8);
                split2(v0.x, v0.y, Ah[mt][0], Al[mt][0]);
                split2(v1.x, v1.y, Ah[mt][1], Al[mt][1]);
                split2(v2.x, v2.y, Ah[mt][2], Al[mt][2]);
                split2(v3.x, v3.y, Ah[mt][3], Al[mt][3]);
            }
            #pragma unroll
            for (int nt = 0; nt < 8; nt++) {
                int n = warp_n * 64 + nt * 8 + gid;
                const __nv_bfloat16* pbh = sBh + n * RSB + kb + 2 * tig;
                const __nv_bfloat16* pbl = sBl + n * RSB + kb + 2 * tig;
                uint32_t bh0 = *(const uint32_t*)(pbh);
                uint32_t bh1 = *(const uint32_t*)(pbh + 8);
                uint32_t bl0 = *(const uint32_t*)(pbl);
                uint32_t bl1 = *(const uint32_t*)(pbl + 8);
                #pragma unroll
                for (int mt = 0; mt < 2; mt++) mma_bf16(acc[mt][nt], Ah[mt], bh0, bh1);
                #pragma unroll
                for (int mt = 0; mt < 2; mt++) mma_bf16(acc[mt][nt], Ah[mt], bl0, bl1);
                #pragma unroll
                for (int mt = 0; mt < 2; mt++) mma_bf16(acc[mt][nt], Al[mt], bh0, bh1);
            }
        }
    }

    // epilogue: tanh + dot with Vw, reduce over n within thread, then over tig
    #pragma unroll
    for (int mt = 0; mt < 2; mt++) {
        float pl = 0.0f, ph = 0.0f;
        #pragma unroll
        for (int nt = 0; nt < 8; nt++) {
            int nb = warp_n * 64 + nt * 8 + 2 * tig;
            pl += tanhf(acc[mt][nt][0] + sWs[nb]     + sUb[nb])     * sVw[nb];
            pl += tanhf(acc[mt][nt][1] + sWs[nb + 1] + sUb[nb + 1]) * sVw[nb + 1];
            ph += tanhf(acc[mt][nt][2] + sWs[nb]     + sUb[nb])     * sVw[nb];
            ph += tanhf(acc[mt][nt][3] + sWs[nb + 1] + sUb[nb + 1]) * sVw[nb + 1];
        }
        pl += __shfl_xor_sync(0xffffffffu, pl, 1);
        pl += __shfl_xor_sync(0xffffffffu, pl, 2);
        ph += __shfl_xor_sync(0xffffffffu, ph, 1);
        ph += __shfl_xor_sync(0xffffffffu, ph, 2);
        if (tig == 0) {
            int r = row0 + warp_m * 32 + mt * 16 + gid;
            atomicAdd(&g_scores[r], pl);
            atomicAdd(&g_scores[r + 8], ph);
        }
    }
}

// ---------------- K4: softmax over S per batch -------------------------------
__global__ void __launch_bounds__(256) k_softmax(float* __restrict__ w_out) {
    __shared__ float red[256];
    const int b   = blockIdx.x;
    const int tid = threadIdx.x;
    const float* sc = g_scores + b * S_;
    float* w = w_out + b * S_;

    float m = -1e30f;
    for (int s = tid; s < S_; s += 256) m = fmaxf(m, sc[s]);
    red[tid] = m; __syncthreads();
    for (int o = 128; o > 0; o >>= 1) {
        if (tid < o) red[tid] = fmaxf(red[tid], red[tid + o]);
        __syncthreads();
    }
    m = red[0];
    __syncthreads();

    float sum = 0.0f;
    for (int s = tid; s < S_; s += 256) {
        float e = expf(sc[s] - m);
        w[s] = e;
        sum += e;
    }
    red[tid] = sum; __syncthreads();
    for (int o = 128; o > 0; o >>= 1) {
        if (tid < o) red[tid] += red[tid + o];
        __syncthreads();
    }
    float inv = 1.0f / red[0];
    for (int s = tid; s < S_; s += 256) w[s] *= inv;
}

// ---------------- K5: context = sum_s w * HS ---------------------------------
__global__ void __launch_bounds__(256) k_context(const float* __restrict__ HS,
                                                 const float* __restrict__ w_in,
                                                 float* __restrict__ ctx) {
    __shared__ float w_sm[256];
    const int tid = threadIdx.x;
    const int b   = blockIdx.y;
    const int s0  = blockIdx.x * 256;

    w_sm[tid] = w_in[b * S_ + s0 + tid];
    __syncthreads();

    const int u = tid * 4;
    float ax = 0.f, ay = 0.f, az = 0.f, aw = 0.f;
    const float* base = HS + ((size_t)b * S_ + s0) * U_ + u;
    for (int s = 0; s < 256; s++) {
        float wv = w_sm[s];
        float4 h = *(const float4*)(base + (size_t)s * U_);
        ax += wv * h.x; ay += wv * h.y; az += wv * h.z; aw += wv * h.w;
    }
    atomicAdd(&ctx[b * U_ + u + 0], ax);
    atomicAdd(&ctx[b * U_ + u + 1], ay);
    atomicAdd(&ctx[b * U_ + u + 2], az);
    atomicAdd(&ctx[b * U_ + u + 3], aw);
}

// ---------------- launch -----------------------------------------------------
extern "C" void kernel_launch(void* const* d_in, const int* in_sizes, int n_in,
                              void* d_out, int out_size) {
    const float* s_prev = (const float*)d_in[0];
    const float* HS     = (const float*)d_in[1];
    const float* Ww     = (const float*)d_in[2];
    const float* Wb     = (const float*)d_in[3];
    const float* Uw     = (const float*)d_in[4];
    const float* Ub     = (const float*)d_in[5];
    const float* Vw     = (const float*)d_in[6];
    const float* Vb     = (const float*)d_in[7];

    float* ctx     = (float*)d_out;            // [64, 1024]
    float* weights = (float*)d_out + B_ * U_;  // [64, 2048, 1]

    cudaFuncSetAttribute(k_scores_mma,
                         cudaFuncAttributeMaxDynamicSharedMemorySize, SMEM_K3);

    // launch order chosen so the profiler's captured launch (#4) is the GEMM
    k_init<<<M_ / 256, 256>>>(Wb, Vb, ctx);
    k_ws<<<dim3(8, 8), 128>>>(s_prev, Ww);
    k_splitB<<<U_ * U_ / 256, 256>>>(Uw);
    k_scores_mma<<<dim3(U_ / BNm, M_ / BMm), 256, SMEM_K3>>>(HS, Ub, Vw);
    k_softmax<<<B_, 256>>>(weights);
    k_context<<<dim3(S_ / 256, B_), 256>>>(HS, weights, ctx);
}

// round 11
// speedup vs baseline: 1.3548x; 1.3070x over previous
#include <cuda_runtime.h>
#include <cuda_bf16.h>
#include <cuda_fp16.h>
#include <cstdint>
#include <math.h>

#define B_  64
#define S_  2048
#define U_  1024
#define M_  (B_ * S_)   // 131072

// ---------------- scratch (device globals; no allocs allowed) ---------------
__device__ float g_Ws[B_ * U_];                     // s_prev @ W_w + W_b
__device__ float g_scores[M_];                      // pre-softmax scores
__device__ __half g_Bhi[U_ * U_];                   // Uw^T hi  [n][k]
__device__ __half g_Blo[U_ * U_];                   // Uw^T lo  [n][k]

// ---------------- K0: init --------------------------------------------------
__global__ void k_init(const float* __restrict__ Wb,
                       const float* __restrict__ Vb,
                       float* __restrict__ ctx_out) {
    int i = blockIdx.x * blockDim.x + threadIdx.x;
    if (i < B_ * U_) { g_Ws[i] = Wb[i & (U_ - 1)]; ctx_out[i] = 0.0f; }
    if (i < M_) g_scores[i] = Vb[0];
}

// ---------------- K1: Ws += s_prev @ W_w ------------------------------------
__global__ void __launch_bounds__(128) k_ws(const float* __restrict__ s_prev,
                                            const float* __restrict__ Ww) {
    __shared__ float s_sm[B_][128];
    const int tid = threadIdx.x;
    const int u   = blockIdx.x * 128 + tid;
    const int k0  = blockIdx.y * 128;
    for (int j = 0; j < 64; j++) {
        int idx = tid + 128 * j;
        s_sm[idx >> 7][idx & 127] = s_prev[(idx >> 7) * U_ + k0 + (idx & 127)];
    }
    __syncthreads();
    float acc[B_];
    #pragma unroll
    for (int b = 0; b < B_; b++) acc[b] = 0.0f;
    for (int kk = 0; kk < 128; kk++) {
        float w = Ww[(k0 + kk) * U_ + u];
        #pragma unroll
        for (int b = 0; b < B_; b++) acc[b] += s_sm[b][kk] * w;
    }
    #pragma unroll
    for (int b = 0; b < B_; b++) atomicAdd(&g_Ws[b * U_ + u], acc[b]);
}

// ---------------- K2: transpose+split Uw -> [n][k] fp16 hi/lo ----------------
__global__ void __launch_bounds__(256) k_splitB(const float* __restrict__ Uw) {
    int i = blockIdx.x * 256 + threadIdx.x;     // 0 .. 1M-1
    int k = i >> 10, n = i & (U_ - 1);
    float x = Uw[k * U_ + n];
    __half h = __float2half_rn(x);
    __half l = __float2half_rn(x - __half2float(h));
    g_Bhi[n * U_ + k] = h;
    g_Blo[n * U_ + k] = l;
}

// ---------------- mma.sync helpers -------------------------------------------
__device__ __forceinline__ uint32_t smem_u32(const void* p) {
    uint32_t a;
    asm("{ .reg .u64 t; cvta.to.shared.u64 t, %1; cvt.u32.u64 %0, t; }"
        : "=r"(a) : "l"(p));
    return a;
}
__device__ __forceinline__ void cp16(uint32_t saddr, const void* g) {
    asm volatile("cp.async.cg.shared.global [%0], [%1], 16;"
                 :: "r"(saddr), "l"(g) : "memory");
}
#define CP_COMMIT() asm volatile("cp.async.commit_group;" ::: "memory")
#define CP_WAIT(N)  asm volatile("cp.async.wait_group %0;" :: "n"(N) : "memory")

__device__ __forceinline__ void mma_f16(float* c, const uint32_t* a,
                                        uint32_t b0, uint32_t b1) {
    asm volatile(
        "mma.sync.aligned.m16n8k16.row.col.f32.f16.f16.f32 "
        "{%0,%1,%2,%3}, {%4,%5,%6,%7}, {%8,%9}, {%0,%1,%2,%3};"
        : "+f"(c[0]), "+f"(c[1]), "+f"(c[2]), "+f"(c[3])
        : "r"(a[0]), "r"(a[1]), "r"(a[2]), "r"(a[3]), "r"(b0), "r"(b1));
}
__device__ __forceinline__ void ldsm_x4(uint32_t& r0, uint32_t& r1,
                                        uint32_t& r2, uint32_t& r3, uint32_t a) {
    asm volatile("ldmatrix.sync.aligned.m8n8.x4.shared.b16 {%0,%1,%2,%3}, [%4];"
                 : "=r"(r0), "=r"(r1), "=r"(r2), "=r"(r3) : "r"(a));
}
__device__ __forceinline__ uint32_t pack_h2(float x0, float x1) {
    __half2 h = __floats2half2_rn(x0, x1);
    return *(uint32_t*)&h;
}

// ---------------- K3: scores GEMM (fp16x2, mma.sync, ldmatrix B) -------------
// C tile BM=128 x BN=128, BK=32; 8 warps (4m x 2n), warp tile 32x64.
// A: fp32 SMEM (converted to fp16 at fragment load), 3-stage.
// B: fp16 hi/lo SMEM via ldmatrix, 2-stage.
#define BMm 128
#define BNm 128
#define BKm 32
#define RSA 36                      // A fp32 row stride (144 B)
#define RSB 40                      // B fp16 row stride (80 B)
#define A_STG (BMm * RSA * 4)       // 18432 B
#define B_HALF (BNm * RSB * 2)      // 10240 B (hi or lo)
#define B_STG (2 * B_HALF)          // 20480 B
#define OFF_A(s) ((s) * A_STG)
#define OFF_Bh(s) (3 * A_STG + (s) * B_STG)
#define OFF_Bl(s) (3 * A_STG + (s) * B_STG + B_HALF)
#define SMEM_K3 (3 * A_STG + 2 * B_STG)     // 96256 B
#define NCHm (U_ / BKm)             // 32 k-chunks

__global__ void __launch_bounds__(256, 2) k_scores_mma(const float* __restrict__ HS,
                                                       const float* __restrict__ Ub,
                                                       const float* __restrict__ Vw) {
    extern __shared__ char sm[];
    __shared__ float sWs[BNm], sUb[BNm], sVw[BNm];

    const int tid  = threadIdx.x;
    const int wid  = tid >> 5;
    const int lane = tid & 31;
    const int gid  = lane >> 2;
    const int tig  = lane & 3;
    const int warp_m = wid & 3;                    // 0..3, 32 rows each
    const int warp_n = wid >> 2;                   // 0..1, 64 cols each

    const int col0 = blockIdx.x * BNm;
    const int row0 = blockIdx.y * BMm;
    const int b    = row0 >> 11;                   // batch (S=2048)

    if (tid < BNm) {
        sWs[tid] = g_Ws[b * U_ + col0 + tid];
        sUb[tid] = Ub[col0 + tid];
        sVw[tid] = Vw[col0 + tid];
    }

    const float* gA = HS + (size_t)row0 * U_;
    const __half* gBh = g_Bhi + (size_t)col0 * U_;
    const __half* gBl = g_Blo + (size_t)col0 * U_;

    const uint32_t sb = smem_u32(sm);

    // per-lane constant ldmatrix offset within a B tile-pair (validated R9):
    //   matrix m = lane>>3 : {0,1,2,3} -> {n+0,k+0},{n+0,k+8},{n+8,k+0},{n+8,k+8}
    const int lm_m = lane >> 3, lm_r = lane & 7;
    const uint32_t lm_off =
        (uint32_t)(((warp_n * 64) + ((lm_m & 2) ? 8 : 0) + lm_r) * RSB
                   + ((lm_m & 1) ? 8 : 0)) * 2;

    // A chunk kc -> stage kc%3 : 128 rows x 128 B = 1024 cp16 (4/thread)
    auto issueA = [&](int kc) {
        if (kc < NCHm) {
            const int kofs = kc * BKm;
            const uint32_t stb = sb + OFF_A(kc % 3);
            #pragma unroll
            for (int i = 0; i < 4; i++) {
                int c = tid + i * 256;             // 0..1023
                int r = c >> 3, q = (c & 7) * 4;   // row, float offset
                cp16(stb + (uint32_t)(r * RSA + q) * 4, gA + (size_t)r * U_ + kofs + q);
            }
        }
        CP_COMMIT();
    };
    // B chunk kc -> stage kc&1 : hi+lo, 128 rows x 64 B each = 512 cp16 (2/thread)
    auto issueB = [&](int kc) {
        if (kc < NCHm) {
            const int kofs = kc * BKm;
            const uint32_t bh = sb + OFF_Bh(kc & 1);
            const uint32_t bl = sb + OFF_Bl(kc & 1);
            #pragma unroll
            for (int i = 0; i < 2; i++) {
                int c = tid + i * 256;             // 0..511
                int r = c >> 2, q = (c & 3) * 8;   // row, fp16 offset
                uint32_t so = (uint32_t)(r * RSB + q) * 2;
                cp16(bh + so, gBh + (size_t)r * U_ + kofs + q);
                cp16(bl + so, gBl + (size_t)r * U_ + kofs + q);
            }
        }
        CP_COMMIT();
    };

    float acc[2][8][4];
    #pragma unroll
    for (int mt = 0; mt < 2; mt++)
        #pragma unroll
        for (int nt = 0; nt < 8; nt++)
            #pragma unroll
            for (int j = 0; j < 4; j++) acc[mt][nt][j] = 0.0f;

    // prologue: groups in FIFO order B0, A0, A1
    issueB(0);
    issueA(0);
    issueA(1);

    for (int kc = 0; kc < NCHm; kc++) {
        CP_WAIT(1);
        __syncthreads();

        // refill keeps FIFO: ...,B(kc),A(kc+1),B(kc+1),A(kc+2)
        issueB(kc + 1);
        issueA(kc + 2);

        const float* sA = (const float*)(sm + OFF_A(kc % 3));
        const uint32_t bh_base = sb + OFF_Bh(kc & 1) + lm_off;
        const uint32_t bl_base = sb + OFF_Bl(kc & 1) + lm_off;

        #pragma unroll
        for (int slab = 0; slab < 2; slab++) {
            const int kb = slab * 16;
            uint32_t Ah[2][4];
            #pragma unroll
            for (int mt = 0; mt < 2; mt++) {
                int r = warp_m * 32 + mt * 16 + gid;
                const float* pa = sA + r * RSA + kb + 2 * tig;
                float2 v0 = *(const float2*)(pa);
                float2 v1 = *(const float2*)(pa + 8 * RSA);
                float2 v2 = *(const float2*)(pa + 8);
                float2 v3 = *(const float2*)(pa + 8 * RSA + 8);
                Ah[mt][0] = pack_h2(v0.x, v0.y);
                Ah[mt][1] = pack_h2(v1.x, v1.y);
                Ah[mt][2] = pack_h2(v2.x, v2.y);
                Ah[mt][3] = pack_h2(v3.x, v3.y);
            }
            #pragma unroll
            for (int ntp = 0; ntp < 4; ntp++) {
                // two n-tiles per ldmatrix.x4 (hi and lo versions of B)
                uint32_t bh0, bh1, bh2, bh3, bl0, bl1, bl2, bl3;
                uint32_t toff = (uint32_t)(ntp * 16 * RSB + kb) * 2;
                ldsm_x4(bh0, bh1, bh2, bh3, bh_base + toff);
                ldsm_x4(bl0, bl1, bl2, bl3, bl_base + toff);
                #pragma unroll
                for (int mt = 0; mt < 2; mt++) {
                    mma_f16(acc[mt][2 * ntp],     Ah[mt], bh0, bh1);
                    mma_f16(acc[mt][2 * ntp],     Ah[mt], bl0, bl1);
                    mma_f16(acc[mt][2 * ntp + 1], Ah[mt], bh2, bh3);
                    mma_f16(acc[mt][2 * ntp + 1], Ah[mt], bl2, bl3);
                }
            }
        }
    }

    // epilogue: tanh + dot with Vw, reduce over n within thread, then over tig
    #pragma unroll
    for (int mt = 0; mt < 2; mt++) {
        float pl = 0.0f, ph = 0.0f;
        #pragma unroll
        for (int nt = 0; nt < 8; nt++) {
            int nb = warp_n * 64 + nt * 8 + 2 * tig;
            pl += tanhf(acc[mt][nt][0] + sWs[nb]     + sUb[nb])     * sVw[nb];
            pl += tanhf(acc[mt][nt][1] + sWs[nb + 1] + sUb[nb + 1]) * sVw[nb + 1];
            ph += tanhf(acc[mt][nt][2] + sWs[nb]     + sUb[nb])     * sVw[nb];
            ph += tanhf(acc[mt][nt][3] + sWs[nb + 1] + sUb[nb + 1]) * sVw[nb + 1];
        }
        pl += __shfl_xor_sync(0xffffffffu, pl, 1);
        pl += __shfl_xor_sync(0xffffffffu, pl, 2);
        ph += __shfl_xor_sync(0xffffffffu, ph, 1);
        ph += __shfl_xor_sync(0xffffffffu, ph, 2);
        if (tig == 0) {
            int r = row0 + warp_m * 32 + mt * 16 + gid;
            atomicAdd(&g_scores[r], pl);
            atomicAdd(&g_scores[r + 8], ph);
        }
    }
}

// ---------------- K4: softmax over S per batch -------------------------------
__global__ void __launch_bounds__(256) k_softmax(float* __restrict__ w_out) {
    __shared__ float red[256];
    const int b   = blockIdx.x;
    const int tid = threadIdx.x;
    const float* sc = g_scores + b * S_;
    float* w = w_out + b * S_;

    float m = -1e30f;
    for (int s = tid; s < S_; s += 256) m = fmaxf(m, sc[s]);
    red[tid] = m; __syncthreads();
    for (int o = 128; o > 0; o >>= 1) {
        if (tid < o) red[tid] = fmaxf(red[tid], red[tid + o]);
        __syncthreads();
    }
    m = red[0];
    __syncthreads();

    float sum = 0.0f;
    for (int s = tid; s < S_; s += 256) {
        float e = expf(sc[s] - m);
        w[s] = e;
        sum += e;
    }
    red[tid] = sum; __syncthreads();
    for (int o = 128; o > 0; o >>= 1) {
        if (tid < o) red[tid] += red[tid + o];
        __syncthreads();
    }
    float inv = 1.0f / red[0];
    for (int s = tid; s < S_; s += 256) w[s] *= inv;
}

// ---------------- K5: context = sum_s w * HS ---------------------------------
__global__ void __launch_bounds__(256) k_context(const float* __restrict__ HS,
                                                 const float* __restrict__ w_in,
                                                 float* __restrict__ ctx) {
    __shared__ float w_sm[256];
    const int tid = threadIdx.x;
    const int b   = blockIdx.y;
    const int s0  = blockIdx.x * 256;

    w_sm[tid] = w_in[b * S_ + s0 + tid];
    __syncthreads();

    const int u = tid * 4;
    float ax = 0.f, ay = 0.f, az = 0.f, aw = 0.f;
    const float* base = HS + ((size_t)b * S_ + s0) * U_ + u;
    for (int s = 0; s < 256; s++) {
        float wv = w_sm[s];
        float4 h = *(const float4*)(base + (size_t)s * U_);
        ax += wv * h.x; ay += wv * h.y; az += wv * h.z; aw += wv * h.w;
    }
    atomicAdd(&ctx[b * U_ + u + 0], ax);
    atomicAdd(&ctx[b * U_ + u + 1], ay);
    atomicAdd(&ctx[b * U_ + u + 2], az);
    atomicAdd(&ctx[b * U_ + u + 3], aw);
}

// ---------------- launch -----------------------------------------------------
extern "C" void kernel_launch(void* const* d_in, const int* in_sizes, int n_in,
                              void* d_out, int out_size) {
    const float* s_prev = (const float*)d_in[0];
    const float* HS     = (const float*)d_in[1];
    const float* Ww     = (const float*)d_in[2];
    const float* Wb     = (const float*)d_in[3];
    const float* Uw     = (const float*)d_in[4];
    const float* Ub     = (const float*)d_in[5];
    const float* Vw     = (const float*)d_in[6];
    const float* Vb     = (const float*)d_in[7];

    float* ctx     = (float*)d_out;            // [64, 1024]
    float* weights = (float*)d_out + B_ * U_;  // [64, 2048, 1]

    cudaFuncSetAttribute(k_scores_mma,
                         cudaFuncAttributeMaxDynamicSharedMemorySize, SMEM_K3);

    // launch order chosen so the profiler's captured launch (#4) is the GEMM
    k_init<<<M_ / 256, 256>>>(Wb, Vb, ctx);
    k_ws<<<dim3(8, 8), 128>>>(s_prev, Ww);
    k_splitB<<<U_ * U_ / 256, 256>>>(Uw);
    k_scores_mma<<<dim3(U_ / BNm, M_ / BMm), 256, SMEM_K3>>>(HS, Ub, Vw);
    k_softmax<<<B_, 256>>>(weights);
    k_context<<<dim3(S_ / 256, B_), 256>>>(HS, weights, ctx);
}

// round 13
// speedup vs baseline: 1.5077x; 1.1128x over previous
#include <cuda_runtime.h>
#include <cuda_fp16.h>
#include <cstdint>
#include <math.h>

#define B_  64
#define S_  2048
#define U_  1024
#define M_  (B_ * S_)   // 131072

// ---------------- scratch (device globals; no allocs allowed) ---------------
__device__ float g_Ws[B_ * U_];                     // s_prev @ W_w + W_b
__device__ float g_scores[M_];                      // pre-softmax scores
__device__ __half g_Ah[(size_t)M_ * U_];            // HS as fp16 (256 MB)
__device__ __half g_Bhi[U_ * U_];                   // Uw^T hi  [n][k]
__device__ __half g_Blo[U_ * U_];                   // Uw^T lo  [n][k]

// ---------------- K0: prep (init + transpose/split Uw) -----------------------
__global__ void __launch_bounds__(256) k_prep(const float* __restrict__ Uw,
                                              const float* __restrict__ Wb,
                                              const float* __restrict__ Vb,
                                              float* __restrict__ ctx_out) {
    int i = blockIdx.x * 256 + threadIdx.x;     // 0 .. 1M-1
    int k = i >> 10, n = i & (U_ - 1);
    float x = Uw[k * U_ + n];
    __half h = __float2half_rn(x);
    g_Bhi[n * U_ + k] = h;
    g_Blo[n * U_ + k] = __float2half_rn(x - __half2float(h));
    if (i < B_ * U_) { g_Ws[i] = Wb[i & (U_ - 1)]; ctx_out[i] = 0.0f; }
    if (i < M_) g_scores[i] = Vb[0];
}

// ---------------- K1: HS -> fp16 ---------------------------------------------
__global__ void __launch_bounds__(256) k_cvtA(const float* __restrict__ HS) {
    size_t i = (size_t)blockIdx.x * 256 + threadIdx.x;
    size_t stride = (size_t)gridDim.x * 256;
    size_t n4 = (size_t)M_ * U_ / 4;
    for (; i < n4; i += stride) {
        float4 v = ((const float4*)HS)[i];
        __half2 h0 = __floats2half2_rn(v.x, v.y);
        __half2 h1 = __floats2half2_rn(v.z, v.w);
        ((__half2*)g_Ah)[i * 2]     = h0;
        ((__half2*)g_Ah)[i * 2 + 1] = h1;
    }
}

// ---------------- K2: Ws += s_prev @ W_w ------------------------------------
__global__ void __launch_bounds__(128) k_ws(const float* __restrict__ s_prev,
                                            const float* __restrict__ Ww) {
    __shared__ float s_sm[B_][128];
    const int tid = threadIdx.x;
    const int u   = blockIdx.x * 128 + tid;
    const int k0  = blockIdx.y * 128;
    for (int j = 0; j < 64; j++) {
        int idx = tid + 128 * j;
        s_sm[idx >> 7][idx & 127] = s_prev[(idx >> 7) * U_ + k0 + (idx & 127)];
    }
    __syncthreads();
    float acc[B_];
    #pragma unroll
    for (int b = 0; b < B_; b++) acc[b] = 0.0f;
    for (int kk = 0; kk < 128; kk++) {
        float w = Ww[(k0 + kk) * U_ + u];
        #pragma unroll
        for (int b = 0; b < B_; b++) acc[b] += s_sm[b][kk] * w;
    }
    #pragma unroll
    for (int b = 0; b < B_; b++) atomicAdd(&g_Ws[b * U_ + u], acc[b]);
}

// ---------------- mma.sync helpers -------------------------------------------
__device__ __forceinline__ uint32_t smem_u32(const void* p) {
    uint32_t a;
    asm("{ .reg .u64 t; cvta.to.shared.u64 t, %1; cvt.u32.u64 %0, t; }"
        : "=r"(a) : "l"(p));
    return a;
}
__device__ __forceinline__ void cp16(uint32_t saddr, const void* g) {
    asm volatile("cp.async.cg.shared.global [%0], [%1], 16;"
                 :: "r"(saddr), "l"(g) : "memory");
}
#define CP_COMMIT() asm volatile("cp.async.commit_group;" ::: "memory")
#define CP_WAIT(N)  asm volatile("cp.async.wait_group %0;" :: "n"(N) : "memory")

__device__ __forceinline__ void mma_f16(float* c, const uint32_t* a,
                                        uint32_t b0, uint32_t b1) {
    asm volatile(
        "mma.sync.aligned.m16n8k16.row.col.f32.f16.f16.f32 "
        "{%0,%1,%2,%3}, {%4,%5,%6,%7}, {%8,%9}, {%0,%1,%2,%3};"
        : "+f"(c[0]), "+f"(c[1]), "+f"(c[2]), "+f"(c[3])
        : "r"(a[0]), "r"(a[1]), "r"(a[2]), "r"(a[3]), "r"(b0), "r"(b1));
}
__device__ __forceinline__ void ldsm_x4(uint32_t& r0, uint32_t& r1,
                                        uint32_t& r2, uint32_t& r3, uint32_t a) {
    asm volatile("ldmatrix.sync.aligned.m8n8.x4.shared.b16 {%0,%1,%2,%3}, [%4];"
                 : "=r"(r0), "=r"(r1), "=r"(r2), "=r"(r3) : "r"(a));
}

// ---------------- K3: scores GEMM (fp16x2, ldmatrix A+B) ---------------------
// C tile BM=128 x BN=128, BK=32; 8 warps (2m x 4n), warp tile 64x32.
// A fp16 SMEM + B fp16 hi/lo SMEM; 3-stage ring, refill AFTER consume barrier.
#define BMm 128
#define BNm 128
#define BKm 32
#define RSH 40                      // fp16 row stride (80 B) for A and B
#define A_TILE (BMm * RSH * 2)      // 10240 B
#define B_HALF (BNm * RSH * 2)      // 10240 B (hi or lo)
#define STG_SZ (A_TILE + 2 * B_HALF)        // 30720 B
#define OFF_BH  A_TILE
#define OFF_BL  (A_TILE + B_HALF)
#define SMEM_K3 (3 * STG_SZ)                // 92160 B
#define NCHm (U_ / BKm)             // 32 k-chunks

__global__ void __launch_bounds__(256, 2) k_scores_mma(const float* __restrict__ Ub,
                                                       const float* __restrict__ Vw) {
    extern __shared__ char sm[];
    __shared__ float sWs[BNm], sUb[BNm], sVw[BNm];

    const int tid  = threadIdx.x;
    const int wid  = tid >> 5;
    const int lane = tid & 31;
    const int gid  = lane >> 2;
    const int tig  = lane & 3;
    const int warp_m = wid & 1;                    // 0..1, 64 rows each
    const int warp_n = wid >> 1;                   // 0..3, 32 cols each

    const int col0 = blockIdx.x * BNm;
    const int row0 = blockIdx.y * BMm;
    const int b    = row0 >> 11;                   // batch (S=2048)

    if (tid < BNm) {
        sWs[tid] = g_Ws[b * U_ + col0 + tid];
        sUb[tid] = Ub[col0 + tid];
        sVw[tid] = Vw[col0 + tid];
    }

    const __half* gA  = g_Ah  + (size_t)row0 * U_;
    const __half* gBh = g_Bhi + (size_t)col0 * U_;
    const __half* gBl = g_Blo + (size_t)col0 * U_;

    const uint32_t sb = smem_u32(sm);

    const int lm_m = lane >> 3, lm_r = lane & 7;
    // B (stored [n][k]): matrices -> {n+0,k+0},{n+0,k+8},{n+8,k+0},{n+8,k+8}
    const uint32_t lmB_off =
        (uint32_t)(((warp_n * 32) + ((lm_m & 2) ? 8 : 0) + lm_r) * RSH
                   + ((lm_m & 1) ? 8 : 0)) * 2;
    // A (stored [m][k]): matrices -> {m+0,k+0},{m+8,k+0},{m+0,k+8},{m+8,k+8}
    const uint32_t lmA_off =
        (uint32_t)(((warp_m * 64) + ((lm_m & 1) ? 8 : 0) + lm_r) * RSH
                   + ((lm_m & 2) ? 8 : 0)) * 2;

    // chunk kc -> stage kc%3 : A 512 cp16 (2/thread); B hi+lo 1024 cp16 (4/thread)
    auto issue = [&](int kc) {
        if (kc < NCHm) {
            const int kofs = kc * BKm;
            const uint32_t stb = sb + (kc % 3) * STG_SZ;
            #pragma unroll
            for (int i = 0; i < 2; i++) {
                int c = tid + i * 256;             // 0..511
                int r = c >> 2, q = (c & 3) * 8;   // row, fp16 offset
                uint32_t so = (uint32_t)(r * RSH + q) * 2;
                cp16(stb + so, gA + (size_t)r * U_ + kofs + q);
                cp16(stb + OFF_BH + so, gBh + (size_t)r * U_ + kofs + q);
                cp16(stb + OFF_BL + so, gBl + (size_t)r * U_ + kofs + q);
            }
        }
        CP_COMMIT();
    };

    float acc[4][4][4];
    #pragma unroll
    for (int mt = 0; mt < 4; mt++)
        #pragma unroll
        for (int nt = 0; nt < 4; nt++)
            #pragma unroll
            for (int j = 0; j < 4; j++) acc[mt][nt][j] = 0.0f;

    issue(0);
    issue(1);
    issue(2);

    for (int kc = 0; kc < NCHm; kc++) {
        // groups issued so far: 0..kc+2 ; <=2 pending => group kc complete
        CP_WAIT(2);
        __syncthreads();

        const uint32_t stg = sb + (kc % 3) * STG_SZ;
        const uint32_t a_base  = stg + lmA_off;
        const uint32_t bh_base = stg + OFF_BH + lmB_off;
        const uint32_t bl_base = stg + OFF_BL + lmB_off;

        #pragma unroll
        for (int slab = 0; slab < 2; slab++) {
            const uint32_t kb = (uint32_t)(slab * 16) * 2;
            uint32_t Ah[4][4];
            #pragma unroll
            for (int mt = 0; mt < 4; mt++) {
                uint32_t toff = (uint32_t)(mt * 16 * RSH) * 2 + kb;
                ldsm_x4(Ah[mt][0], Ah[mt][1], Ah[mt][2], Ah[mt][3], a_base + toff);
            }
            #pragma unroll
            for (int ntp = 0; ntp < 2; ntp++) {
                uint32_t bh0, bh1, bh2, bh3, bl0, bl1, bl2, bl3;
                uint32_t toff = (uint32_t)(ntp * 16 * RSH) * 2 + kb;
                ldsm_x4(bh0, bh1, bh2, bh3, bh_base + toff);
                ldsm_x4(bl0, bl1, bl2, bl3, bl_base + toff);
                #pragma unroll
                for (int mt = 0; mt < 4; mt++) {
                    mma_f16(acc[mt][2 * ntp],     Ah[mt], bh0, bh1);
                    mma_f16(acc[mt][2 * ntp],     Ah[mt], bl0, bl1);
                    mma_f16(acc[mt][2 * ntp + 1], Ah[mt], bh2, bh3);
                    mma_f16(acc[mt][2 * ntp + 1], Ah[mt], bl2, bl3);
                }
            }
        }

        // all warps done reading stage kc%3 before it is refilled
        __syncthreads();
        issue(kc + 3);   // writes stage (kc+3)%3 == kc%3, now safe
    }

    // epilogue: tanh + dot with Vw, reduce over n within thread, then over tig
    #pragma unroll
    for (int mt = 0; mt < 4; mt++) {
        float pl = 0.0f, ph = 0.0f;
        #pragma unroll
        for (int nt = 0; nt < 4; nt++) {
            int nb = warp_n * 32 + nt * 8 + 2 * tig;
            pl += tanhf(acc[mt][nt][0] + sWs[nb]     + sUb[nb])     * sVw[nb];
            pl += tanhf(acc[mt][nt][1] + sWs[nb + 1] + sUb[nb + 1]) * sVw[nb + 1];
            ph += tanhf(acc[mt][nt][2] + sWs[nb]     + sUb[nb])     * sVw[nb];
            ph += tanhf(acc[mt][nt][3] + sWs[nb + 1] + sUb[nb + 1]) * sVw[nb + 1];
        }
        pl += __shfl_xor_sync(0xffffffffu, pl, 1);
        pl += __shfl_xor_sync(0xffffffffu, pl, 2);
        ph += __shfl_xor_sync(0xffffffffu, ph, 1);
        ph += __shfl_xor_sync(0xffffffffu, ph, 2);
        if (tig == 0) {
            int r = row0 + warp_m * 64 + mt * 16 + gid;
            atomicAdd(&g_scores[r], pl);
            atomicAdd(&g_scores[r + 8], ph);
        }
    }
}

// ---------------- K4: softmax over S per batch -------------------------------
__global__ void __launch_bounds__(256) k_softmax(float* __restrict__ w_out) {
    __shared__ float red[256];
    const int b   = blockIdx.x;
    const int tid = threadIdx.x;
    const float* sc = g_scores + b * S_;
    float* w = w_out + b * S_;

    float m = -1e30f;
    for (int s = tid; s < S_; s += 256) m = fmaxf(m, sc[s]);
    red[tid] = m; __syncthreads();
    for (int o = 128; o > 0; o >>= 1) {
        if (tid < o) red[tid] = fmaxf(red[tid], red[tid + o]);
        __syncthreads();
    }
    m = red[0];
    __syncthreads();

    float sum = 0.0f;
    for (int s = tid; s < S_; s += 256) {
        float e = expf(sc[s] - m);
        w[s] = e;
        sum += e;
    }
    red[tid] = sum; __syncthreads();
    for (int o = 128; o > 0; o >>= 1) {
        if (tid < o) red[tid] += red[tid + o];
        __syncthreads();
    }
    float inv = 1.0f / red[0];
    for (int s = tid; s < S_; s += 256) w[s] *= inv;
}

// ---------------- K5: context = sum_s w * HS ---------------------------------
__global__ void __launch_bounds__(256) k_context(const float* __restrict__ HS,
                                                 const float* __restrict__ w_in,
                                                 float* __restrict__ ctx) {
    __shared__ float w_sm[256];
    const int tid = threadIdx.x;
    const int b   = blockIdx.y;
    const int s0  = blockIdx.x * 256;

    w_sm[tid] = w_in[b * S_ + s0 + tid];
    __syncthreads();

    const int u = tid * 4;
    float ax = 0.f, ay = 0.f, az = 0.f, aw = 0.f;
    const float* base = HS + ((size_t)b * S_ + s0) * U_ + u;
    for (int s = 0; s < 256; s++) {
        float wv = w_sm[s];
        float4 h = *(const float4*)(base + (size_t)s * U_);
        ax += wv * h.x; ay += wv * h.y; az += wv * h.z; aw += wv * h.w;
    }
    atomicAdd(&ctx[b * U_ + u + 0], ax);
    atomicAdd(&ctx[b * U_ + u + 1], ay);
    atomicAdd(&ctx[b * U_ + u + 2], az);
    atomicAdd(&ctx[b * U_ + u + 3], aw);
}

// ---------------- launch -----------------------------------------------------
extern "C" void kernel_launch(void* const* d_in, const int* in_sizes, int n_in,
                              void* d_out, int out_size) {
    const float* s_prev = (const float*)d_in[0];
    const float* HS     = (const float*)d_in[1];
    const float* Ww     = (const float*)d_in[2];
    const float* Wb     = (const float*)d_in[3];
    const float* Uw     = (const float*)d_in[4];
    const float* Ub     = (const float*)d_in[5];
    const float* Vw     = (const float*)d_in[6];
    const float* Vb     = (const float*)d_in[7];

    float* ctx     = (float*)d_out;            // [64, 1024]
    float* weights = (float*)d_out + B_ * U_;  // [64, 2048, 1]

    cudaFuncSetAttribute(k_scores_mma,
                         cudaFuncAttributeMaxDynamicSharedMemorySize, SMEM_K3);

    // launch order keeps the GEMM as launch #4 for the profiler
    k_prep<<<U_ * U_ / 256, 256>>>(Uw, Wb, Vb, ctx);
    k_cvtA<<<8192, 256>>>(HS);
    k_ws<<<dim3(8, 8), 128>>>(s_prev, Ww);
    k_scores_mma<<<dim3(U_ / BNm, M_ / BMm), 256, SMEM_K3>>>(Ub, Vw);
    k_softmax<<<B_, 256>>>(weights);
    k_context<<<dim3(S_ / 256, B_), 256>>>(HS, weights, ctx);
}

// round 14
// speedup vs baseline: 2.3342x; 1.5482x over previous
#include <cuda_runtime.h>
#include <cuda_fp16.h>
#include <cstdint>
#include <math.h>

#define B_  64
#define S_  2048
#define U_  1024
#define M_  (B_ * S_)   // 131072

// ---------------- scratch (device globals; no allocs allowed) ---------------
__device__ float g_Ws[B_ * U_];                     // s_prev @ W_w + W_b
__device__ float g_scores[M_];                      // pre-softmax scores
__device__ __half g_Ah[(size_t)M_ * U_];            // HS as fp16 (256 MB)
__device__ __half g_Bh[U_ * U_];                    // Uw^T fp16 [n][k]

// ---------------- K0: prep (init + transpose Uw) -----------------------------
__global__ void __launch_bounds__(256) k_prep(const float* __restrict__ Uw,
                                              const float* __restrict__ Wb,
                                              const float* __restrict__ Vb,
                                              float* __restrict__ ctx_out) {
    int i = blockIdx.x * 256 + threadIdx.x;     // 0 .. 1M-1
    int k = i >> 10, n = i & (U_ - 1);
    g_Bh[n * U_ + k] = __float2half_rn(Uw[k * U_ + n]);
    if (i < B_ * U_) { g_Ws[i] = Wb[i & (U_ - 1)]; ctx_out[i] = 0.0f; }
    if (i < M_) g_scores[i] = Vb[0];
}

// ---------------- K1: HS -> fp16 ---------------------------------------------
__global__ void __launch_bounds__(256) k_cvtA(const float* __restrict__ HS) {
    size_t i = (size_t)blockIdx.x * 256 + threadIdx.x;
    size_t stride = (size_t)gridDim.x * 256;
    size_t n4 = (size_t)M_ * U_ / 4;
    for (; i < n4; i += stride) {
        float4 v = ((const float4*)HS)[i];
        ((__half2*)g_Ah)[i * 2]     = __floats2half2_rn(v.x, v.y);
        ((__half2*)g_Ah)[i * 2 + 1] = __floats2half2_rn(v.z, v.w);
    }
}

// ---------------- K2: Ws += s_prev @ W_w ------------------------------------
__global__ void __launch_bounds__(128) k_ws(const float* __restrict__ s_prev,
                                            const float* __restrict__ Ww) {
    __shared__ float s_sm[B_][128];
    const int tid = threadIdx.x;
    const int u   = blockIdx.x * 128 + tid;
    const int k0  = blockIdx.y * 128;
    for (int j = 0; j < 64; j++) {
        int idx = tid + 128 * j;
        s_sm[idx >> 7][idx & 127] = s_prev[(idx >> 7) * U_ + k0 + (idx & 127)];
    }
    __syncthreads();
    float acc[B_];
    #pragma unroll
    for (int b = 0; b < B_; b++) acc[b] = 0.0f;
    for (int kk = 0; kk < 128; kk++) {
        float w = Ww[(k0 + kk) * U_ + u];
        #pragma unroll
        for (int b = 0; b < B_; b++) acc[b] += s_sm[b][kk] * w;
    }
    #pragma unroll
    for (int b = 0; b < B_; b++) atomicAdd(&g_Ws[b * U_ + u], acc[b]);
}

// ---------------- mma.sync helpers -------------------------------------------
__device__ __forceinline__ uint32_t smem_u32(const void* p) {
    uint32_t a;
    asm("{ .reg .u64 t; cvta.to.shared.u64 t, %1; cvt.u32.u64 %0, t; }"
        : "=r"(a) : "l"(p));
    return a;
}
__device__ __forceinline__ void cp16(uint32_t saddr, const void* g) {
    asm volatile("cp.async.cg.shared.global [%0], [%1], 16;"
                 :: "r"(saddr), "l"(g) : "memory");
}
#define CP_COMMIT() asm volatile("cp.async.commit_group;" ::: "memory")
#define CP_WAIT(N)  asm volatile("cp.async.wait_group %0;" :: "n"(N) : "memory")

__device__ __forceinline__ void mma_f16(float* c, const uint32_t* a,
                                        uint32_t b0, uint32_t b1) {
    asm volatile(
        "mma.sync.aligned.m16n8k16.row.col.f32.f16.f16.f32 "
        "{%0,%1,%2,%3}, {%4,%5,%6,%7}, {%8,%9}, {%0,%1,%2,%3};"
        : "+f"(c[0]), "+f"(c[1]), "+f"(c[2]), "+f"(c[3])
        : "r"(a[0]), "r"(a[1]), "r"(a[2]), "r"(a[3]), "r"(b0), "r"(b1));
}
__device__ __forceinline__ void ldsm_x4(uint32_t& r0, uint32_t& r1,
                                        uint32_t& r2, uint32_t& r3, uint32_t a) {
    asm volatile("ldmatrix.sync.aligned.m8n8.x4.shared.b16 {%0,%1,%2,%3}, [%4];"
                 : "=r"(r0), "=r"(r1), "=r"(r2), "=r"(r3) : "r"(a));
}

// ---------------- K3: scores GEMM (fp16 single product) ----------------------
// C tile BM=128 x BN=128, BK=32; 8 warps (2m x 4n), warp tile 64x32.
// 3-stage ring, ONE barrier per chunk: wait, sync, issue(kc+2), consume.
#define BMm 128
#define BNm 128
#define BKm 32
#define RSH 40                      // fp16 row stride (80 B)
#define A_TILE (BMm * RSH * 2)      // 10240 B
#define B_TILE (BNm * RSH * 2)      // 10240 B
#define STG_SZ (A_TILE + B_TILE)    // 20480 B
#define OFF_B   A_TILE
#define SMEM_K3 (3 * STG_SZ)        // 61440 B
#define NCHm (U_ / BKm)             // 32 k-chunks

__global__ void __launch_bounds__(256, 2) k_scores_mma(const float* __restrict__ Ub,
                                                       const float* __restrict__ Vw) {
    extern __shared__ char sm[];
    __shared__ float sWs[BNm], sUb[BNm], sVw[BNm];

    const int tid  = threadIdx.x;
    const int wid  = tid >> 5;
    const int lane = tid & 31;
    const int gid  = lane >> 2;
    const int tig  = lane & 3;
    const int warp_m = wid & 1;                    // 0..1, 64 rows each
    const int warp_n = wid >> 1;                   // 0..3, 32 cols each

    const int col0 = blockIdx.x * BNm;
    const int row0 = blockIdx.y * BMm;
    const int b    = row0 >> 11;                   // batch (S=2048)

    if (tid < BNm) {
        sWs[tid] = g_Ws[b * U_ + col0 + tid];
        sUb[tid] = Ub[col0 + tid];
        sVw[tid] = Vw[col0 + tid];
    }

    const __half* gA = g_Ah + (size_t)row0 * U_;
    const __half* gB = g_Bh + (size_t)col0 * U_;

    const uint32_t sb = smem_u32(sm);

    const int lm_m = lane >> 3, lm_r = lane & 7;
    // B (stored [n][k]): matrices -> {n+0,k+0},{n+0,k+8},{n+8,k+0},{n+8,k+8}
    const uint32_t lmB_off =
        (uint32_t)(((warp_n * 32) + ((lm_m & 2) ? 8 : 0) + lm_r) * RSH
                   + ((lm_m & 1) ? 8 : 0)) * 2;
    // A (stored [m][k]): matrices -> {m+0,k+0},{m+8,k+0},{m+0,k+8},{m+8,k+8}
    const uint32_t lmA_off =
        (uint32_t)(((warp_m * 64) + ((lm_m & 1) ? 8 : 0) + lm_r) * RSH
                   + ((lm_m & 2) ? 8 : 0)) * 2;

    // chunk kc -> stage kc%3 : A 512 cp16 (2/thread); B 512 cp16 (2/thread)
    auto issue = [&](int kc) {
        if (kc < NCHm) {
            const int kofs = kc * BKm;
            const uint32_t stb = sb + (kc % 3) * STG_SZ;
            #pragma unroll
            for (int i = 0; i < 2; i++) {
                int c = tid + i * 256;             // 0..511
                int r = c >> 2, q = (c & 3) * 8;   // row, fp16 offset
                uint32_t so = (uint32_t)(r * RSH + q) * 2;
                cp16(stb + so, gA + (size_t)r * U_ + kofs + q);
                cp16(stb + OFF_B + so, gB + (size_t)r * U_ + kofs + q);
            }
        }
        CP_COMMIT();
    };

    float acc[4][4][4];
    #pragma unroll
    for (int mt = 0; mt < 4; mt++)
        #pragma unroll
        for (int nt = 0; nt < 4; nt++)
            #pragma unroll
            for (int j = 0; j < 4; j++) acc[mt][nt][j] = 0.0f;

    issue(0);
    issue(1);

    for (int kc = 0; kc < NCHm; kc++) {
        // groups issued: 0..kc+1 ; <=1 pending => group kc complete
        CP_WAIT(1);
        __syncthreads();
        // issue(kc+2) writes stage (kc+2)%3 == (kc-1)%3 — all warps finished
        // reading it before the barrier above. In-flight groups kc+1, kc+2
        // never touch stage kc%3 being consumed below.
        issue(kc + 2);

        const uint32_t stg = sb + (kc % 3) * STG_SZ;
        const uint32_t a_base = stg + lmA_off;
        const uint32_t b_base = stg + OFF_B + lmB_off;

        #pragma unroll
        for (int slab = 0; slab < 2; slab++) {
            const uint32_t kb = (uint32_t)(slab * 16) * 2;
            uint32_t Ah[4][4];
            #pragma unroll
            for (int mt = 0; mt < 4; mt++) {
                uint32_t toff = (uint32_t)(mt * 16 * RSH) * 2 + kb;
                ldsm_x4(Ah[mt][0], Ah[mt][1], Ah[mt][2], Ah[mt][3], a_base + toff);
            }
            #pragma unroll
            for (int ntp = 0; ntp < 2; ntp++) {
                uint32_t b0, b1, b2, b3;
                uint32_t toff = (uint32_t)(ntp * 16 * RSH) * 2 + kb;
                ldsm_x4(b0, b1, b2, b3, b_base + toff);
                #pragma unroll
                for (int mt = 0; mt < 4; mt++) {
                    mma_f16(acc[mt][2 * ntp],     Ah[mt], b0, b1);
                    mma_f16(acc[mt][2 * ntp + 1], Ah[mt], b2, b3);
                }
            }
        }
    }

    // epilogue: tanh + dot with Vw, reduce over n within thread, then over tig
    #pragma unroll
    for (int mt = 0; mt < 4; mt++) {
        float pl = 0.0f, ph = 0.0f;
        #pragma unroll
        for (int nt = 0; nt < 4; nt++) {
            int nb = warp_n * 32 + nt * 8 + 2 * tig;
            pl += tanhf(acc[mt][nt][0] + sWs[nb]     + sUb[nb])     * sVw[nb];
            pl += tanhf(acc[mt][nt][1] + sWs[nb + 1] + sUb[nb + 1]) * sVw[nb + 1];
            ph += tanhf(acc[mt][nt][2] + sWs[nb]     + sUb[nb])     * sVw[nb];
            ph += tanhf(acc[mt][nt][3] + sWs[nb + 1] + sUb[nb + 1]) * sVw[nb + 1];
        }
        pl += __shfl_xor_sync(0xffffffffu, pl, 1);
        pl += __shfl_xor_sync(0xffffffffu, pl, 2);
        ph += __shfl_xor_sync(0xffffffffu, ph, 1);
        ph += __shfl_xor_sync(0xffffffffu, ph, 2);
        if (tig == 0) {
            int r = row0 + warp_m * 64 + mt * 16 + gid;
            atomicAdd(&g_scores[r], pl);
            atomicAdd(&g_scores[r + 8], ph);
        }
    }
}

// ---------------- K4: softmax over S per batch -------------------------------
__global__ void __launch_bounds__(256) k_softmax(float* __restrict__ w_out) {
    __shared__ float red[256];
    const int b   = blockIdx.x;
    const int tid = threadIdx.x;
    const float* sc = g_scores + b * S_;
    float* w = w_out + b * S_;

    float m = -1e30f;
    for (int s = tid; s < S_; s += 256) m = fmaxf(m, sc[s]);
    red[tid] = m; __syncthreads();
    for (int o = 128; o > 0; o >>= 1) {
        if (tid < o) red[tid] = fmaxf(red[tid], red[tid + o]);
        __syncthreads();
    }
    m = red[0];
    __syncthreads();

    float sum = 0.0f;
    for (int s = tid; s < S_; s += 256) {
        float e = expf(sc[s] - m);
        w[s] = e;
        sum += e;
    }
    red[tid] = sum; __syncthreads();
    for (int o = 128; o > 0; o >>= 1) {
        if (tid < o) red[tid] += red[tid + o];
        __syncthreads();
    }
    float inv = 1.0f / red[0];
    for (int s = tid; s < S_; s += 256) w[s] *= inv;
}

// ---------------- K5: context = sum_s w * HS ---------------------------------
__global__ void __launch_bounds__(256) k_context(const float* __restrict__ HS,
                                                 const float* __restrict__ w_in,
                                                 float* __restrict__ ctx) {
    __shared__ float w_sm[256];
    const int tid = threadIdx.x;
    const int b   = blockIdx.y;
    const int s0  = blockIdx.x * 256;

    w_sm[tid] = w_in[b * S_ + s0 + tid];
    __syncthreads();

    const int u = tid * 4;
    float ax = 0.f, ay = 0.f, az = 0.f, aw = 0.f;
    const float* base = HS + ((size_t)b * S_ + s0) * U_ + u;
    for (int s = 0; s < 256; s++) {
        float wv = w_sm[s];
        float4 h = *(const float4*)(base + (size_t)s * U_);
        ax += wv * h.x; ay += wv * h.y; az += wv * h.z; aw += wv * h.w;
    }
    atomicAdd(&ctx[b * U_ + u + 0], ax);
    atomicAdd(&ctx[b * U_ + u + 1], ay);
    atomicAdd(&ctx[b * U_ + u + 2], az);
    atomicAdd(&ctx[b * U_ + u + 3], aw);
}

// ---------------- launch -----------------------------------------------------
extern "C" void kernel_launch(void* const* d_in, const int* in_sizes, int n_in,
                              void* d_out, int out_size) {
    const float* s_prev = (const float*)d_in[0];
    const float* HS     = (const float*)d_in[1];
    const float* Ww     = (const float*)d_in[2];
    const float* Wb     = (const float*)d_in[3];
    const float* Uw     = (const float*)d_in[4];
    const float* Ub     = (const float*)d_in[5];
    const float* Vw     = (const float*)d_in[6];
    const float* Vb     = (const float*)d_in[7];

    float* ctx     = (float*)d_out;            // [64, 1024]
    float* weights = (float*)d_out + B_ * U_;  // [64, 2048, 1]

    cudaFuncSetAttribute(k_scores_mma,
                         cudaFuncAttributeMaxDynamicSharedMemorySize, SMEM_K3);

    // launch order keeps the GEMM as launch #4 for the profiler
    k_prep<<<U_ * U_ / 256, 256>>>(Uw, Wb, Vb, ctx);
    k_cvtA<<<8192, 256>>>(HS);
    k_ws<<<dim3(8, 8), 128>>>(s_prev, Ww);
    k_scores_mma<<<dim3(U_ / BNm, M_ / BMm), 256, SMEM_K3>>>(Ub, Vw);
    k_softmax<<<B_, 256>>>(weights);
    k_context<<<dim3(S_ / 256, B_), 256>>>(HS, weights, ctx);
}

// round 15
// speedup vs baseline: 2.4998x; 1.0709x over previous
#include <cuda_runtime.h>
#include <cuda_fp16.h>
#include <cstdint>
#include <math.h>

#define B_  64
#define S_  2048
#define U_  1024
#define M_  (B_ * S_)   // 131072

// ---------------- scratch (device globals; no allocs allowed) ---------------
__device__ float g_Ws[B_ * U_];                     // s_prev @ W_w + W_b
__device__ float g_scores[M_];                      // pre-softmax scores
__device__ __half g_Ah[(size_t)M_ * U_];            // HS as fp16 (256 MB)
__device__ __half g_Bh[U_ * U_];                    // Uw^T fp16 [n][k]

// ---------------- K0: prep (init + transpose Uw) -----------------------------
__global__ void __launch_bounds__(256) k_prep(const float* __restrict__ Uw,
                                              const float* __restrict__ Wb,
                                              const float* __restrict__ Vb,
                                              float* __restrict__ ctx_out) {
    int i = blockIdx.x * 256 + threadIdx.x;     // 0 .. 1M-1
    int k = i >> 10, n = i & (U_ - 1);
    g_Bh[n * U_ + k] = __float2half_rn(Uw[k * U_ + n]);
    if (i < B_ * U_) { g_Ws[i] = Wb[i & (U_ - 1)]; ctx_out[i] = 0.0f; }
    if (i < M_) g_scores[i] = Vb[0];
}

// ---------------- K1: HS -> fp16 ---------------------------------------------
__global__ void __launch_bounds__(256) k_cvtA(const float* __restrict__ HS) {
    size_t i = (size_t)blockIdx.x * 256 + threadIdx.x;
    size_t stride = (size_t)gridDim.x * 256;
    size_t n4 = (size_t)M_ * U_ / 4;
    for (; i < n4; i += stride) {
        float4 v = ((const float4*)HS)[i];
        ((__half2*)g_Ah)[i * 2]     = __floats2half2_rn(v.x, v.y);
        ((__half2*)g_Ah)[i * 2 + 1] = __floats2half2_rn(v.z, v.w);
    }
}

// ---------------- K2: Ws += s_prev @ W_w ------------------------------------
__global__ void __launch_bounds__(128) k_ws(const float* __restrict__ s_prev,
                                            const float* __restrict__ Ww) {
    __shared__ float s_sm[B_][128];
    const int tid = threadIdx.x;
    const int u   = blockIdx.x * 128 + tid;
    const int k0  = blockIdx.y * 128;
    for (int j = 0; j < 64; j++) {
        int idx = tid + 128 * j;
        s_sm[idx >> 7][idx & 127] = s_prev[(idx >> 7) * U_ + k0 + (idx & 127)];
    }
    __syncthreads();
    float acc[B_];
    #pragma unroll
    for (int b = 0; b < B_; b++) acc[b] = 0.0f;
    for (int kk = 0; kk < 128; kk++) {
        float w = Ww[(k0 + kk) * U_ + u];
        #pragma unroll
        for (int b = 0; b < B_; b++) acc[b] += s_sm[b][kk] * w;
    }
    #pragma unroll
    for (int b = 0; b < B_; b++) atomicAdd(&g_Ws[b * U_ + u], acc[b]);
}

// ---------------- mma.sync helpers -------------------------------------------
__device__ __forceinline__ uint32_t smem_u32(const void* p) {
    uint32_t a;
    asm("{ .reg .u64 t; cvta.to.shared.u64 t, %1; cvt.u32.u64 %0, t; }"
        : "=r"(a) : "l"(p));
    return a;
}
__device__ __forceinline__ void cp16(uint32_t saddr, const void* g) {
    asm volatile("cp.async.cg.shared.global [%0], [%1], 16;"
                 :: "r"(saddr), "l"(g) : "memory");
}
#define CP_COMMIT() asm volatile("cp.async.commit_group;" ::: "memory")
#define CP_WAIT(N)  asm volatile("cp.async.wait_group %0;" :: "n"(N) : "memory")

__device__ __forceinline__ void mma_f16(float* c, const uint32_t* a,
                                        uint32_t b0, uint32_t b1) {
    asm volatile(
        "mma.sync.aligned.m16n8k16.row.col.f32.f16.f16.f32 "
        "{%0,%1,%2,%3}, {%4,%5,%6,%7}, {%8,%9}, {%0,%1,%2,%3};"
        : "+f"(c[0]), "+f"(c[1]), "+f"(c[2]), "+f"(c[3])
        : "r"(a[0]), "r"(a[1]), "r"(a[2]), "r"(a[3]), "r"(b0), "r"(b1));
}
__device__ __forceinline__ void ldsm_x4(uint32_t& r0, uint32_t& r1,
                                        uint32_t& r2, uint32_t& r3, uint32_t a) {
    asm volatile("ldmatrix.sync.aligned.m8n8.x4.shared.b16 {%0,%1,%2,%3}, [%4];"
                 : "=r"(r0), "=r"(r1), "=r"(r2), "=r"(r3) : "r"(a));
}

// ---------------- K3: scores GEMM (fp16 single product, BK=64) ---------------
// C tile BM=128 x BN=128, BK=64; 8 warps (2m x 4n), warp tile 64x32.
// 3-stage ring, ONE barrier per chunk: wait, sync, issue(kc+2), consume.
#define BMm 128
#define BNm 128
#define BKm 64
#define RSH 72                      // fp16 row stride (144 B), pad 8
#define A_TILE (BMm * RSH * 2)      // 18432 B
#define B_TILE (BNm * RSH * 2)      // 18432 B
#define STG_SZ (A_TILE + B_TILE)    // 36864 B
#define OFF_B   A_TILE
#define SMEM_K3 (3 * STG_SZ)        // 110592 B
#define NCHm (U_ / BKm)             // 16 k-chunks

__global__ void __launch_bounds__(256, 2) k_scores_mma(const float* __restrict__ Ub,
                                                       const float* __restrict__ Vw) {
    extern __shared__ char sm[];
    __shared__ float sWs[BNm], sUb[BNm], sVw[BNm];

    const int tid  = threadIdx.x;
    const int wid  = tid >> 5;
    const int lane = tid & 31;
    const int gid  = lane >> 2;
    const int tig  = lane & 3;
    const int warp_m = wid & 1;                    // 0..1, 64 rows each
    const int warp_n = wid >> 1;                   // 0..3, 32 cols each

    const int col0 = blockIdx.x * BNm;
    const int row0 = blockIdx.y * BMm;
    const int b    = row0 >> 11;                   // batch (S=2048)

    if (tid < BNm) {
        sWs[tid] = g_Ws[b * U_ + col0 + tid];
        sUb[tid] = Ub[col0 + tid];
        sVw[tid] = Vw[col0 + tid];
    }

    const __half* gA = g_Ah + (size_t)row0 * U_;
    const __half* gB = g_Bh + (size_t)col0 * U_;

    const uint32_t sb = smem_u32(sm);

    const int lm_m = lane >> 3, lm_r = lane & 7;
    // B (stored [n][k]): matrices -> {n+0,k+0},{n+0,k+8},{n+8,k+0},{n+8,k+8}
    const uint32_t lmB_off =
        (uint32_t)(((warp_n * 32) + ((lm_m & 2) ? 8 : 0) + lm_r) * RSH
                   + ((lm_m & 1) ? 8 : 0)) * 2;
    // A (stored [m][k]): matrices -> {m+0,k+0},{m+8,k+0},{m+0,k+8},{m+8,k+8}
    const uint32_t lmA_off =
        (uint32_t)(((warp_m * 64) + ((lm_m & 1) ? 8 : 0) + lm_r) * RSH
                   + ((lm_m & 2) ? 8 : 0)) * 2;

    // chunk kc -> stage kc%3 : A 1024 cp16 (4/thread); B 1024 cp16 (4/thread)
    auto issue = [&](int kc) {
        if (kc < NCHm) {
            const int kofs = kc * BKm;
            const uint32_t stb = sb + (kc % 3) * STG_SZ;
            #pragma unroll
            for (int i = 0; i < 4; i++) {
                int c = tid + i * 256;             // 0..1023
                int r = c >> 3, q = (c & 7) * 8;   // row, fp16 offset
                uint32_t so = (uint32_t)(r * RSH + q) * 2;
                cp16(stb + so, gA + (size_t)r * U_ + kofs + q);
                cp16(stb + OFF_B + so, gB + (size_t)r * U_ + kofs + q);
            }
        }
        CP_COMMIT();
    };

    float acc[4][4][4];
    #pragma unroll
    for (int mt = 0; mt < 4; mt++)
        #pragma unroll
        for (int nt = 0; nt < 4; nt++)
            #pragma unroll
            for (int j = 0; j < 4; j++) acc[mt][nt][j] = 0.0f;

    issue(0);
    issue(1);

    for (int kc = 0; kc < NCHm; kc++) {
        // groups issued: 0..kc+1 ; <=1 pending => group kc complete
        CP_WAIT(1);
        __syncthreads();
        // issue(kc+2) writes stage (kc+2)%3 == (kc-1)%3 — all warps finished
        // reading it before the barrier above.
        issue(kc + 2);

        const uint32_t stg = sb + (kc % 3) * STG_SZ;
        const uint32_t a_base = stg + lmA_off;
        const uint32_t b_base = stg + OFF_B + lmB_off;

        #pragma unroll
        for (int slab = 0; slab < 4; slab++) {
            const uint32_t kb = (uint32_t)(slab * 16) * 2;
            uint32_t Ah[4][4];
            #pragma unroll
            for (int mt = 0; mt < 4; mt++) {
                uint32_t toff = (uint32_t)(mt * 16 * RSH) * 2 + kb;
                ldsm_x4(Ah[mt][0], Ah[mt][1], Ah[mt][2], Ah[mt][3], a_base + toff);
            }
            #pragma unroll
            for (int ntp = 0; ntp < 2; ntp++) {
                uint32_t b0, b1, b2, b3;
                uint32_t toff = (uint32_t)(ntp * 16 * RSH) * 2 + kb;
                ldsm_x4(b0, b1, b2, b3, b_base + toff);
                #pragma unroll
                for (int mt = 0; mt < 4; mt++) {
                    mma_f16(acc[mt][2 * ntp],     Ah[mt], b0, b1);
                    mma_f16(acc[mt][2 * ntp + 1], Ah[mt], b2, b3);
                }
            }
        }
    }

    // epilogue: tanh + dot with Vw, reduce over n within thread, then over tig
    #pragma unroll
    for (int mt = 0; mt < 4; mt++) {
        float pl = 0.0f, ph = 0.0f;
        #pragma unroll
        for (int nt = 0; nt < 4; nt++) {
            int nb = warp_n * 32 + nt * 8 + 2 * tig;
            pl += tanhf(acc[mt][nt][0] + sWs[nb]     + sUb[nb])     * sVw[nb];
            pl += tanhf(acc[mt][nt][1] + sWs[nb + 1] + sUb[nb + 1]) * sVw[nb + 1];
            ph += tanhf(acc[mt][nt][2] + sWs[nb]     + sUb[nb])     * sVw[nb];
            ph += tanhf(acc[mt][nt][3] + sWs[nb + 1] + sUb[nb + 1]) * sVw[nb + 1];
        }
        pl += __shfl_xor_sync(0xffffffffu, pl, 1);
        pl += __shfl_xor_sync(0xffffffffu, pl, 2);
        ph += __shfl_xor_sync(0xffffffffu, ph, 1);
        ph += __shfl_xor_sync(0xffffffffu, ph, 2);
        if (tig == 0) {
            int r = row0 + warp_m * 64 + mt * 16 + gid;
            atomicAdd(&g_scores[r], pl);
            atomicAdd(&g_scores[r + 8], ph);
        }
    }
}

// ---------------- K4: softmax over S per batch -------------------------------
__global__ void __launch_bounds__(256) k_softmax(float* __restrict__ w_out) {
    __shared__ float red[256];
    const int b   = blockIdx.x;
    const int tid = threadIdx.x;
    const float* sc = g_scores + b * S_;
    float* w = w_out + b * S_;

    float m = -1e30f;
    for (int s = tid; s < S_; s += 256) m = fmaxf(m, sc[s]);
    red[tid] = m; __syncthreads();
    for (int o = 128; o > 0; o >>= 1) {
        if (tid < o) red[tid] = fmaxf(red[tid], red[tid + o]);
        __syncthreads();
    }
    m = red[0];
    __syncthreads();

    float sum = 0.0f;
    for (int s = tid; s < S_; s += 256) {
        float e = expf(sc[s] - m);
        w[s] = e;
        sum += e;
    }
    red[tid] = sum; __syncthreads();
    for (int o = 128; o > 0; o >>= 1) {
        if (tid < o) red[tid] += red[tid + o];
        __syncthreads();
    }
    float inv = 1.0f / red[0];
    for (int s = tid; s < S_; s += 256) w[s] *= inv;
}

// ---------------- K5: context = sum_s w * HS ---------------------------------
__global__ void __launch_bounds__(256) k_context(const float* __restrict__ HS,
                                                 const float* __restrict__ w_in,
                                                 float* __restrict__ ctx) {
    __shared__ float w_sm[256];
    const int tid = threadIdx.x;
    const int b   = blockIdx.y;
    const int s0  = blockIdx.x * 256;

    w_sm[tid] = w_in[b * S_ + s0 + tid];
    __syncthreads();

    const int u = tid * 4;
    float ax = 0.f, ay = 0.f, az = 0.f, aw = 0.f;
    const float* base = HS + ((size_t)b * S_ + s0) * U_ + u;
    for (int s = 0; s < 256; s++) {
        float wv = w_sm[s];
        float4 h = *(const float4*)(base + (size_t)s * U_);
        ax += wv * h.x; ay += wv * h.y; az += wv * h.z; aw += wv * h.w;
    }
    atomicAdd(&ctx[b * U_ + u + 0], ax);
    atomicAdd(&ctx[b * U_ + u + 1], ay);
    atomicAdd(&ctx[b * U_ + u + 2], az);
    atomicAdd(&ctx[b * U_ + u + 3], aw);
}

// ---------------- launch -----------------------------------------------------
extern "C" void kernel_launch(void* const* d_in, const int* in_sizes, int n_in,
                              void* d_out, int out_size) {
    const float* s_prev = (const float*)d_in[0];
    const float* HS     = (const float*)d_in[1];
    const float* Ww     = (const float*)d_in[2];
    const float* Wb     = (const float*)d_in[3];
    const float* Uw     = (const float*)d_in[4];
    const float* Ub     = (const float*)d_in[5];
    const float* Vw     = (const float*)d_in[6];
    const float* Vb     = (const float*)d_in[7];

    float* ctx     = (float*)d_out;            // [64, 1024]
    float* weights = (float*)d_out + B_ * U_;  // [64, 2048, 1]

    cudaFuncSetAttribute(k_scores_mma,
                         cudaFuncAttributeMaxDynamicSharedMemorySize, SMEM_K3);

    // launch order keeps the GEMM as launch #4 for the profiler
    k_prep<<<U_ * U_ / 256, 256>>>(Uw, Wb, Vb, ctx);
    k_cvtA<<<8192, 256>>>(HS);
    k_ws<<<dim3(8, 8), 128>>>(s_prev, Ww);
    k_scores_mma<<<dim3(U_ / BNm, M_ / BMm), 256, SMEM_K3>>>(Ub, Vw);
    k_softmax<<<B_, 256>>>(weights);
    k_context<<<dim3(S_ / 256, B_), 256>>>(HS, weights, ctx);
}